// round 14
// baseline (speedup 1.0000x reference)
#include <cuda_runtime.h>
#include <cuda_fp16.h>
#include <cstdint>

#define NN 100000
#define NE 600000
#define D  128
#define WPAD 136            // weight row width (272B rows)

// smem (bytes): X0 0 | X1 10240 | h 20480(34816) | W0/W1/W2 55296+i*8704 | idx 81408.
// LN staging (128*528=67584) aliases X+h+W (all dead after layer-3 gemm).
#define XSTR   80u
#define XOFF(b) ((uint32_t)(b) * 10240u)
#define SM_H    20480u
#define WBUF(i) (55296u + (uint32_t)(i) * 8704u)
#define SM_STG  0u
#define SM_IDXS 81408u
#define SM_IDXR 81920u
#define SMEM_TOTAL 82432

__device__ float g_agg[(size_t)NN * D];
// stacked fp16 weights (rows x 272B): [0,384) ew1 (W1a|W1b|W1c) | [384,512) ew2 |
// [512,640) ew3 | [640,896) nw1[0:256] | [896,1024) nw2 | [1024,1152) nw3
__device__ __half g_w[1152 * WPAD];
// precomputed node projections, fp16: row n = [ P_a(n)=nf.W1a (128) | P_b(n)=nf.W1b (128) ]
__device__ __half g_P[(size_t)NN * 256];

__global__ void zero_agg_kernel() {
    size_t i = (size_t)blockIdx.x * blockDim.x + threadIdx.x;
    ((float4*)g_agg)[i] = make_float4(0.f, 0.f, 0.f, 0.f);
}

__global__ void prep_weights(const float* __restrict__ ew1, const float* __restrict__ ew2,
                             const float* __restrict__ ew3, const float* __restrict__ nw1,
                             const float* __restrict__ nw2, const float* __restrict__ nw3) {
    int idx = blockIdx.x * 256 + threadIdx.x;
    if (idx >= 1152 * WPAD) return;
    int r = idx / WPAD, c = idx % WPAD;
    float v = 0.f;
    if (c < 128) {
        if (r < 384)       v = ew1[r * 128 + c];
        else if (r < 512)  v = ew2[(r - 384) * 128 + c];
        else if (r < 640)  v = ew3[(r - 512) * 128 + c];
        else if (r < 896)  v = nw1[(r - 640) * 128 + c];
        else if (r < 1024) v = nw2[(r - 896) * 128 + c];
        else               v = nw3[(r - 1024) * 128 + c];
    }
    g_w[idx] = __float2half_rn(v);
}

// ---------------- helpers ----------------
__device__ __forceinline__ void mma16816(float* c, const uint32_t* a, const uint32_t* b) {
    asm volatile(
        "mma.sync.aligned.m16n8k16.row.col.f32.f16.f16.f32 "
        "{%0,%1,%2,%3}, {%4,%5,%6,%7}, {%8,%9}, {%0,%1,%2,%3};"
        : "+f"(c[0]), "+f"(c[1]), "+f"(c[2]), "+f"(c[3])
        : "r"(a[0]), "r"(a[1]), "r"(a[2]), "r"(a[3]), "r"(b[0]), "r"(b[1]));
}
__device__ __forceinline__ void ldm_a(uint32_t* r, uint32_t addr) {
    asm volatile("ldmatrix.sync.aligned.m8n8.x4.shared.b16 {%0,%1,%2,%3}, [%4];"
                 : "=r"(r[0]), "=r"(r[1]), "=r"(r[2]), "=r"(r[3]) : "r"(addr));
}
__device__ __forceinline__ void ldm_bt4(uint32_t* r, uint32_t addr) {
    asm volatile("ldmatrix.sync.aligned.m8n8.x4.trans.shared.b16 {%0,%1,%2,%3}, [%4];"
                 : "=r"(r[0]), "=r"(r[1]), "=r"(r[2]), "=r"(r[3]) : "r"(addr));
}
__device__ __forceinline__ void cp16(uint32_t s, const void* g) {
    asm volatile("cp.async.cg.shared.global [%0], [%1], 16;" :: "r"(s), "l"(g));
}
#define CP_COMMIT() asm volatile("cp.async.commit_group;")
template <int N>
__device__ __forceinline__ void cp_wait() { asm volatile("cp.async.wait_group %0;" :: "n"(N)); }

__device__ __forceinline__ uint32_t hpack(__half a, __half b) {
    __half2 t = __halves2half2(a, b);
    return *reinterpret_cast<uint32_t*>(&t);
}

// stage one 32-row fp16 weight chunk (8704B) via cp.async
__device__ __forceinline__ void stage_w(uint32_t sb, uint32_t woff, int wrow, int tid) {
    const char* sw = (const char*)(g_w + (size_t)wrow * WPAD);
#pragma unroll
    for (int i = 0; i < 3; i++) {
        int j = tid + i * 256;
        if (j < 544) cp16(sb + woff + (uint32_t)j * 16, sw + j * 16);
    }
    CP_COMMIT();
}

// one 32-k chunk: acc[4][4][4] += A[128 x 32] * W[32 x 128]  (warp tile 64x32)
__device__ __forceinline__ void gemm_chunk(uint32_t sb, uint32_t a_off, uint32_t astr,
                                           uint32_t kbase, uint32_t w_off,
                                           int lane, int wm, int wn, float acc[4][4][4]) {
    uint32_t bw[4][4];
    uint32_t brow = (uint32_t)lane * 272u;
#pragma unroll
    for (int nt = 0; nt < 4; nt++) {
        uint32_t nb = (uint32_t)(wn * 32 + nt * 8) * 2;
        ldm_bt4(bw[nt], sb + w_off + brow + nb);
    }
#pragma unroll
    for (int ks = 0; ks < 2; ks++) {
        uint32_t ah[4][4];
        uint32_t colb = (kbase + (uint32_t)ks * 16 + (uint32_t)((lane >> 4) << 3)) * 2;
#pragma unroll
        for (int mt = 0; mt < 4; mt++) {
            uint32_t row = (uint32_t)(wm * 64 + mt * 16 + (lane & 15));
            ldm_a(ah[mt], sb + a_off + row * astr + colb);
        }
#pragma unroll
        for (int mt = 0; mt < 4; mt++)
#pragma unroll
            for (int nt = 0; nt < 4; nt++)
                mma16816(acc[mt][nt], ah[mt], &bw[nt][ks * 2]);
    }
}

// bias + relu -> fp16 h image (stride 272B)
__device__ __forceinline__ void epi_relu(float acc[4][4][4], const float* __restrict__ bias,
                                         char* smem, int lane, int wm, int wn) {
#pragma unroll
    for (int mt = 0; mt < 4; mt++)
#pragma unroll
        for (int nt = 0; nt < 4; nt++) {
            int n0 = wn * 32 + nt * 8 + (lane & 3) * 2;
            float2 bv = *(const float2*)(bias + n0);
            int r0 = wm * 64 + mt * 16 + (lane >> 2);
            float v0 = fmaxf(acc[mt][nt][0] + bv.x, 0.f);
            float v1 = fmaxf(acc[mt][nt][1] + bv.y, 0.f);
            float v2 = fmaxf(acc[mt][nt][2] + bv.x, 0.f);
            float v3 = fmaxf(acc[mt][nt][3] + bv.y, 0.f);
            *(uint32_t*)(smem + SM_H + r0 * 272 + n0 * 2) =
                hpack(__float2half_rn(v0), __float2half_rn(v1));
            *(uint32_t*)(smem + SM_H + (r0 + 8) * 272 + n0 * 2) =
                hpack(__float2half_rn(v2), __float2half_rn(v3));
        }
}

// layer3: bias only -> fp32 staging (stride 528B)
__device__ __forceinline__ void epi_f32(float acc[4][4][4], const float* __restrict__ bias,
                                        char* smem, int lane, int wm, int wn) {
#pragma unroll
    for (int mt = 0; mt < 4; mt++)
#pragma unroll
        for (int nt = 0; nt < 4; nt++) {
            int n0 = wn * 32 + nt * 8 + (lane & 3) * 2;
            float2 bv = *(const float2*)(bias + n0);
            int r0 = wm * 64 + mt * 16 + (lane >> 2);
            *(float2*)(smem + SM_STG + r0 * 528 + n0 * 4) =
                make_float2(acc[mt][nt][0] + bv.x, acc[mt][nt][1] + bv.y);
            *(float2*)(smem + SM_STG + (r0 + 8) * 528 + n0 * 4) =
                make_float2(acc[mt][nt][2] + bv.x, acc[mt][nt][3] + bv.y);
        }
}

// ---------------- P kernel: g_P[n] = [ nf.W1a | nf.W1b ], fp16 ----------------
__global__ void __launch_bounds__(256, 2) p_kernel(const float* __restrict__ nf) {
    extern __shared__ char smem[];
    const uint32_t sb = (uint32_t)__cvta_generic_to_shared(smem);
    const int tid = threadIdx.x, lane = tid & 31, wid = tid >> 5;
    const int wm = wid >> 2, wn = wid & 3;
    const size_t base = (size_t)blockIdx.x * 128;
    const int pass = blockIdx.y;            // 0: W1a (rows 0..128), 1: W1b (rows 128..256)
    const int grow = tid >> 1, q = tid & 1;

    float4 pre[4];
    auto ldg_chunk = [&](int g) {
        size_t ge = base + grow;
        bool zero = (ge >= NN);
        const float* src = nf + (zero ? 0 : ge * D) + g * 32 + q * 16;
#pragma unroll
        for (int i = 0; i < 4; i++)
            pre[i] = zero ? make_float4(0.f, 0.f, 0.f, 0.f) : *(const float4*)(src + i * 4);
    };
    auto sts_chunk = [&](int buf) {
        uint4 h0, h1;
        h0.x = hpack(__float2half_rn(pre[0].x), __float2half_rn(pre[0].y));
        h0.y = hpack(__float2half_rn(pre[0].z), __float2half_rn(pre[0].w));
        h0.z = hpack(__float2half_rn(pre[1].x), __float2half_rn(pre[1].y));
        h0.w = hpack(__float2half_rn(pre[1].z), __float2half_rn(pre[1].w));
        h1.x = hpack(__float2half_rn(pre[2].x), __float2half_rn(pre[2].y));
        h1.y = hpack(__float2half_rn(pre[2].z), __float2half_rn(pre[2].w));
        h1.z = hpack(__float2half_rn(pre[3].x), __float2half_rn(pre[3].y));
        h1.w = hpack(__float2half_rn(pre[3].z), __float2half_rn(pre[3].w));
        uint32_t off = XOFF(buf) + (uint32_t)grow * XSTR + (uint32_t)q * 32;
        *(uint4*)(smem + off)      = h0;
        *(uint4*)(smem + off + 16) = h1;
    };

    float acc[4][4][4];
#pragma unroll
    for (int mt = 0; mt < 4; mt++)
#pragma unroll
        for (int nt = 0; nt < 4; nt++)
#pragma unroll
            for (int i = 0; i < 4; i++) acc[mt][nt][i] = 0.f;

    const int WR0 = pass * 128;
    ldg_chunk(0); sts_chunk(0); ldg_chunk(1);
    stage_w(sb, WBUF(0), WR0, tid);
    stage_w(sb, WBUF(1), WR0 + 32, tid);
    cp_wait<1>();
    __syncthreads();

    for (int g = 0; g < 4; g++) {
        if (g + 1 < 4) sts_chunk((g + 1) & 1);
        if (g + 2 < 4) ldg_chunk(g + 2);
        if (g + 2 < 4) stage_w(sb, WBUF((g + 2) % 3), WR0 + (g + 2) * 32, tid);
        gemm_chunk(sb, XOFF(g & 1), XSTR, 0u, WBUF(g % 3), lane, wm, wn, acc);
        if (g + 2 < 4) cp_wait<1>(); else cp_wait<0>();
        __syncthreads();
    }

#pragma unroll
    for (int mt = 0; mt < 4; mt++)
#pragma unroll
        for (int nt = 0; nt < 4; nt++) {
            int n0 = wn * 32 + nt * 8 + (lane & 3) * 2;
            int r0 = wm * 64 + mt * 16 + (lane >> 2);
            if (base + r0 < NN)
                *(uint32_t*)&g_P[(base + r0) * 256 + pass * 128 + n0] =
                    hpack(__float2half_rn(acc[mt][nt][0]), __float2half_rn(acc[mt][nt][1]));
            if (base + r0 + 8 < NN)
                *(uint32_t*)&g_P[(base + r0 + 8) * 256 + pass * 128 + n0] =
                    hpack(__float2half_rn(acc[mt][nt][2]), __float2half_rn(acc[mt][nt][3]));
        }
}

// ---------------- main MLP kernels ----------------
template <bool EDGE>
__global__ void __launch_bounds__(256, 2) mlp_kernel(
    const float* __restrict__ nf, const float* __restrict__ ef,
    const int* __restrict__ snd, const int* __restrict__ rcv,
    const float* __restrict__ b1, const float* __restrict__ b2, const float* __restrict__ b3,
    const float* __restrict__ gamma, const float* __restrict__ beta,
    float* __restrict__ out) {
    extern __shared__ char smem[];
    const uint32_t sb = (uint32_t)__cvta_generic_to_shared(smem);
    const int tid = threadIdx.x, lane = tid & 31, wid = tid >> 5;
    const int wm = wid >> 2, wn = wid & 3;
    const size_t base = (size_t)blockIdx.x * 128;
    const size_t LIM = EDGE ? NE : NN;

    int* sidx = (int*)(smem + SM_IDXS);
    int* ridx = (int*)(smem + SM_IDXR);
    if (EDGE) {
        size_t ge = base + (tid & 127);
        int v = (ge < NE) ? ((tid < 128) ? snd[ge] : rcv[ge]) : 0;
        if (tid < 128) sidx[tid] = v; else ridx[tid - 128] = v;
    }
    __syncthreads();

    const int grow = tid >> 1, q = tid & 1;   // gather: 2 threads/row, 16 floats each

    float4 pre[4];                            // prefetched gather regs
    auto ldg_chunk = [&](int g) {
        const float* src;
        bool zero = false;
        size_t ge = base + grow;
        int col0 = (g & 3) * 32 + q * 16;
        if (EDGE) {                            // layer-1 input is ef only
            zero = (ge >= NE);
            src = ef + (zero ? 0 : ge * D) + col0;
        } else {
            int seg = g >> 2;
            zero = (ge >= NN);
            src = (seg == 0 ? nf : g_agg) + (zero ? 0 : ge * D) + col0;
        }
#pragma unroll
        for (int i = 0; i < 4; i++)
            pre[i] = zero ? make_float4(0.f, 0.f, 0.f, 0.f) : *(const float4*)(src + i * 4);
    };
    auto sts_chunk = [&](int buf) {
        uint4 h0, h1;
        h0.x = hpack(__float2half_rn(pre[0].x), __float2half_rn(pre[0].y));
        h0.y = hpack(__float2half_rn(pre[0].z), __float2half_rn(pre[0].w));
        h0.z = hpack(__float2half_rn(pre[1].x), __float2half_rn(pre[1].y));
        h0.w = hpack(__float2half_rn(pre[1].z), __float2half_rn(pre[1].w));
        h1.x = hpack(__float2half_rn(pre[2].x), __float2half_rn(pre[2].y));
        h1.y = hpack(__float2half_rn(pre[2].z), __float2half_rn(pre[2].w));
        h1.z = hpack(__float2half_rn(pre[3].x), __float2half_rn(pre[3].y));
        h1.w = hpack(__float2half_rn(pre[3].z), __float2half_rn(pre[3].w));
        uint32_t off = XOFF(buf) + (uint32_t)grow * XSTR + (uint32_t)q * 32;
        *(uint4*)(smem + off)      = h0;
        *(uint4*)(smem + off + 16) = h1;
    };
    auto clear_acc = [](float acc[4][4][4]) {
#pragma unroll
        for (int mt = 0; mt < 4; mt++)
#pragma unroll
            for (int nt = 0; nt < 4; nt++)
#pragma unroll
                for (int i = 0; i < 4; i++) acc[mt][nt][i] = 0.f;
    };

    const int L1 = EDGE ? 4 : 8;        // 32-k chunks in layer 1
    const int NCH = L1 + 8;             // + 4 (L2) + 4 (L3)
    const int WR0 = EDGE ? 256 : 640;   // first stacked weight row (edge: W1c)

    float acc[4][4][4];

    // ---- acc init: edges start from gathered P_a[snd] + P_b[rcv] ----
    if (EDGE) {
#pragma unroll
        for (int mt = 0; mt < 4; mt++) {
            int rbase = wm * 64 + mt * 16 + (lane >> 2);
#pragma unroll
            for (int hh = 0; hh < 2; hh++) {
                int r = rbase + hh * 8;
                const __half* pa = g_P + (size_t)sidx[r] * 256;
                const __half* pb = g_P + (size_t)ridx[r] * 256 + 128;
#pragma unroll
                for (int nt = 0; nt < 4; nt++) {
                    int n0 = wn * 32 + nt * 8 + (lane & 3) * 2;
                    float2 fa = __half22float2(*(const __half2*)(pa + n0));
                    float2 fb = __half22float2(*(const __half2*)(pb + n0));
                    acc[mt][nt][hh * 2 + 0] = fa.x + fb.x;
                    acc[mt][nt][hh * 2 + 1] = fa.y + fb.y;
                }
            }
        }
    } else {
        clear_acc(acc);
    }

    // ---- prologue: X chunks 0,1 and W chunks 0,1 in flight ----
    ldg_chunk(0);
    sts_chunk(0);
    ldg_chunk(1);
    stage_w(sb, WBUF(0), WR0, tid);
    stage_w(sb, WBUF(1), WR0 + 32, tid);
    cp_wait<1>();                        // W0 complete
    __syncthreads();

    // ---- fused chunk loop: ONE barrier per chunk ----
    for (int g = 0; g < NCH; g++) {
        if (g == L1 || g == L1 + 4) {    // layer boundary: write h, then barrier
            epi_relu(acc, (g == L1) ? b1 : b2, smem, lane, wm, wn);
            clear_acc(acc);
            __syncthreads();
        }
        // prefetches — all independent of gemm(g)
        if (g + 1 < L1) sts_chunk((g + 1) & 1);          // regs hold chunk g+1
        if (g + 2 < L1) ldg_chunk(g + 2);
        if (g + 2 < NCH) stage_w(sb, WBUF((g + 2) % 3), WR0 + (g + 2) * 32, tid);

        if (g < L1) gemm_chunk(sb, XOFF(g & 1), XSTR, 0u, WBUF(g % 3), lane, wm, wn, acc);
        else gemm_chunk(sb, SM_H, 272u, (uint32_t)((g - L1) & 3) * 32u,
                        WBUF(g % 3), lane, wm, wn, acc);

        if (g + 2 < NCH) cp_wait<1>(); else cp_wait<0>();
        __syncthreads();                 // X(g+1), W(g+1) visible; gemm(g) done CTA-wide
    }

    epi_f32(acc, b3, smem, lane, wm, wn);   // staging aliases dead X+h+W
    __syncthreads();

    // LN + residual (+ scatter for edges): 16 threads/row, 8 rows per group
    const int ccg = tid & 15, ecg = tid >> 4;
    float4 g0 = *(const float4*)(gamma + ccg * 8), g1 = *(const float4*)(gamma + ccg * 8 + 4);
    float4 t0 = *(const float4*)(beta + ccg * 8),  t1 = *(const float4*)(beta + ccg * 8 + 4);
    float gv[8] = {g0.x, g0.y, g0.z, g0.w, g1.x, g1.y, g1.z, g1.w};
    float bv[8] = {t0.x, t0.y, t0.z, t0.w, t1.x, t1.y, t1.z, t1.w};
#pragma unroll
    for (int ei = 0; ei < 8; ei++) {
        int el = ecg * 8 + ei;
        size_t ge = base + el;
        float4 p0 = *(float4*)(smem + SM_STG + (uint32_t)el * 528 + ccg * 32);
        float4 p1 = *(float4*)(smem + SM_STG + (uint32_t)el * 528 + ccg * 32 + 16);
        float v[8] = {p0.x, p0.y, p0.z, p0.w, p1.x, p1.y, p1.z, p1.w};
        float s = 0.f, s2 = 0.f;
#pragma unroll
        for (int c = 0; c < 8; c++) { s += v[c]; s2 += v[c] * v[c]; }
#pragma unroll
        for (int m = 8; m >= 1; m >>= 1) {
            s  += __shfl_xor_sync(0xffffffffu, s, m);
            s2 += __shfl_xor_sync(0xffffffffu, s2, m);
        }
        if (ge >= LIM) continue;
        float mu = s * (1.f / D), var = s2 * (1.f / D) - mu * mu;
        float rstd = rsqrtf(fmaxf(var, 0.f) + 1e-5f);
        float nrm[8];
#pragma unroll
        for (int c = 0; c < 8; c++) nrm[c] = (v[c] - mu) * rstd * gv[c] + bv[c];
        if (EDGE) {
            float* ap = g_agg + (size_t)ridx[el] * D + ccg * 8;
            asm volatile("red.global.add.v4.f32 [%0], {%1,%2,%3,%4};" ::
                         "l"(ap), "f"(nrm[0]), "f"(nrm[1]), "f"(nrm[2]), "f"(nrm[3]) : "memory");
            asm volatile("red.global.add.v4.f32 [%0], {%1,%2,%3,%4};" ::
                         "l"(ap + 4), "f"(nrm[4]), "f"(nrm[5]), "f"(nrm[6]), "f"(nrm[7]) : "memory");
        }
        const float* res = (EDGE ? ef : nf) + ge * D + ccg * 8;
        float4 e0 = *(const float4*)res, e1 = *(const float4*)(res + 4);
        float* op = out + ge * D + ccg * 8;
        *(float4*)op       = make_float4(nrm[0] + e0.x, nrm[1] + e0.y, nrm[2] + e0.z, nrm[3] + e0.w);
        *(float4*)(op + 4) = make_float4(nrm[4] + e1.x, nrm[5] + e1.y, nrm[6] + e1.z, nrm[7] + e1.w);
    }
}

extern "C" void kernel_launch(void* const* d_in, const int* in_sizes, int n_in,
                              void* d_out, int out_size) {
    const float* nf  = (const float*)d_in[0];
    const float* ef  = (const float*)d_in[1];
    const int*   snd = (const int*)d_in[2];
    const int*   rcv = (const int*)d_in[3];
    const float* ew1 = (const float*)d_in[4];
    const float* eb1 = (const float*)d_in[5];
    const float* ew2 = (const float*)d_in[6];
    const float* eb2 = (const float*)d_in[7];
    const float* ew3 = (const float*)d_in[8];
    const float* eb3 = (const float*)d_in[9];
    const float* eg  = (const float*)d_in[10];
    const float* ebt = (const float*)d_in[11];
    const float* nw1 = (const float*)d_in[12];
    const float* nb1 = (const float*)d_in[13];
    const float* nw2 = (const float*)d_in[14];
    const float* nb2 = (const float*)d_in[15];
    const float* nw3 = (const float*)d_in[16];
    const float* nb3 = (const float*)d_in[17];
    const float* ng  = (const float*)d_in[18];
    const float* nbt = (const float*)d_in[19];

    float* out_n = (float*)d_out;
    float* out_e = out_n + (size_t)NN * D;

    cudaFuncSetAttribute(mlp_kernel<true>,  cudaFuncAttributeMaxDynamicSharedMemorySize, SMEM_TOTAL);
    cudaFuncSetAttribute(mlp_kernel<false>, cudaFuncAttributeMaxDynamicSharedMemorySize, SMEM_TOTAL);
    cudaFuncSetAttribute(p_kernel, cudaFuncAttributeMaxDynamicSharedMemorySize, SMEM_TOTAL);

    prep_weights<<<612, 256>>>(ew1, ew2, ew3, nw1, nw2, nw3);
    zero_agg_kernel<<<NN * D / 4 / 256, 256>>>();
    p_kernel<<<dim3((NN + 127) / 128, 2), 256, SMEM_TOTAL>>>(nf);
    mlp_kernel<true><<<(NE + 127) / 128, 256, SMEM_TOTAL>>>(nf, ef, snd, rcv,
                                                            eb1, eb2, eb3, eg, ebt, out_e);
    mlp_kernel<false><<<(NN + 127) / 128, 256, SMEM_TOTAL>>>(nf, ef, snd, rcv,
                                                             nb1, nb2, nb3, ng, nbt, out_n);
}

// round 15
// speedup vs baseline: 1.2222x; 1.2222x over previous
#include <cuda_runtime.h>
#include <cuda_fp16.h>
#include <cstdint>

#define NN 100000
#define NE 600000
#define D  128
#define WPAD 136            // weight row width (272B rows)

// smem (bytes): X0 0 | X1 10240 | h 20480(34816) | W0/W1/W2 55296+i*8704 | idx 81408.
// PSUM (128 x 272B = 34816) aliases X0/X1/h-head (dead before prologue).
// LN staging (128*528=67584) aliases X+h+W (dead after layer-3 gemm).
#define XSTR   80u
#define XOFF(b) ((uint32_t)(b) * 10240u)
#define SM_H    20480u
#define WBUF(i) (55296u + (uint32_t)(i) * 8704u)
#define SM_STG  0u
#define SM_PSUM 0u
#define SM_IDXS 81408u
#define SM_IDXR 81920u
#define SMEM_TOTAL 82432

__device__ float g_agg[(size_t)NN * D];
// stacked fp16 weights (rows x 272B): [0,384) ew1 (W1a|W1b|W1c) | [384,512) ew2 |
// [512,640) ew3 | [640,896) nw1[0:256] | [896,1024) nw2 | [1024,1152) nw3
__device__ __half g_w[1152 * WPAD];
// precomputed node projections, fp16: row n = [ P_a(n)=nf.W1a (128) | P_b(n)=nf.W1b (128) ]
__device__ __half g_P[(size_t)NN * 256];

__global__ void zero_agg_kernel() {
    size_t i = (size_t)blockIdx.x * blockDim.x + threadIdx.x;
    ((float4*)g_agg)[i] = make_float4(0.f, 0.f, 0.f, 0.f);
}

__global__ void prep_weights(const float* __restrict__ ew1, const float* __restrict__ ew2,
                             const float* __restrict__ ew3, const float* __restrict__ nw1,
                             const float* __restrict__ nw2, const float* __restrict__ nw3) {
    int idx = blockIdx.x * 256 + threadIdx.x;
    if (idx >= 1152 * WPAD) return;
    int r = idx / WPAD, c = idx % WPAD;
    float v = 0.f;
    if (c < 128) {
        if (r < 384)       v = ew1[r * 128 + c];
        else if (r < 512)  v = ew2[(r - 384) * 128 + c];
        else if (r < 640)  v = ew3[(r - 512) * 128 + c];
        else if (r < 896)  v = nw1[(r - 640) * 128 + c];
        else if (r < 1024) v = nw2[(r - 896) * 128 + c];
        else               v = nw3[(r - 1024) * 128 + c];
    }
    g_w[idx] = __float2half_rn(v);
}

// ---------------- helpers ----------------
__device__ __forceinline__ void mma16816(float* c, const uint32_t* a, const uint32_t* b) {
    asm volatile(
        "mma.sync.aligned.m16n8k16.row.col.f32.f16.f16.f32 "
        "{%0,%1,%2,%3}, {%4,%5,%6,%7}, {%8,%9}, {%0,%1,%2,%3};"
        : "+f"(c[0]), "+f"(c[1]), "+f"(c[2]), "+f"(c[3])
        : "r"(a[0]), "r"(a[1]), "r"(a[2]), "r"(a[3]), "r"(b[0]), "r"(b[1]));
}
__device__ __forceinline__ void ldm_a(uint32_t* r, uint32_t addr) {
    asm volatile("ldmatrix.sync.aligned.m8n8.x4.shared.b16 {%0,%1,%2,%3}, [%4];"
                 : "=r"(r[0]), "=r"(r[1]), "=r"(r[2]), "=r"(r[3]) : "r"(addr));
}
__device__ __forceinline__ void ldm_bt4(uint32_t* r, uint32_t addr) {
    asm volatile("ldmatrix.sync.aligned.m8n8.x4.trans.shared.b16 {%0,%1,%2,%3}, [%4];"
                 : "=r"(r[0]), "=r"(r[1]), "=r"(r[2]), "=r"(r[3]) : "r"(addr));
}
__device__ __forceinline__ void cp16(uint32_t s, const void* g) {
    asm volatile("cp.async.cg.shared.global [%0], [%1], 16;" :: "r"(s), "l"(g));
}
#define CP_COMMIT() asm volatile("cp.async.commit_group;")
template <int N>
__device__ __forceinline__ void cp_wait() { asm volatile("cp.async.wait_group %0;" :: "n"(N)); }

__device__ __forceinline__ uint32_t hpack(__half a, __half b) {
    __half2 t = __halves2half2(a, b);
    return *reinterpret_cast<uint32_t*>(&t);
}
__device__ __forceinline__ uint32_t hadd2u(uint32_t a, uint32_t b) {
    __half2 r = __hadd2(*reinterpret_cast<__half2*>(&a), *reinterpret_cast<__half2*>(&b));
    return *reinterpret_cast<uint32_t*>(&r);
}

// stage one 32-row fp16 weight chunk (8704B) via cp.async
__device__ __forceinline__ void stage_w(uint32_t sb, uint32_t woff, int wrow, int tid) {
    const char* sw = (const char*)(g_w + (size_t)wrow * WPAD);
#pragma unroll
    for (int i = 0; i < 3; i++) {
        int j = tid + i * 256;
        if (j < 544) cp16(sb + woff + (uint32_t)j * 16, sw + j * 16);
    }
    CP_COMMIT();
}

// one 32-k chunk: acc[4][4][4] += A[128 x 32] * W[32 x 128]  (warp tile 64x32)
__device__ __forceinline__ void gemm_chunk(uint32_t sb, uint32_t a_off, uint32_t astr,
                                           uint32_t kbase, uint32_t w_off,
                                           int lane, int wm, int wn, float acc[4][4][4]) {
    uint32_t bw[4][4];
    uint32_t brow = (uint32_t)lane * 272u;
#pragma unroll
    for (int nt = 0; nt < 4; nt++) {
        uint32_t nb = (uint32_t)(wn * 32 + nt * 8) * 2;
        ldm_bt4(bw[nt], sb + w_off + brow + nb);
    }
#pragma unroll
    for (int ks = 0; ks < 2; ks++) {
        uint32_t ah[4][4];
        uint32_t colb = (kbase + (uint32_t)ks * 16 + (uint32_t)((lane >> 4) << 3)) * 2;
#pragma unroll
        for (int mt = 0; mt < 4; mt++) {
            uint32_t row = (uint32_t)(wm * 64 + mt * 16 + (lane & 15));
            ldm_a(ah[mt], sb + a_off + row * astr + colb);
        }
#pragma unroll
        for (int mt = 0; mt < 4; mt++)
#pragma unroll
            for (int nt = 0; nt < 4; nt++)
                mma16816(acc[mt][nt], ah[mt], &bw[nt][ks * 2]);
    }
}

// bias + relu -> fp16 h image (stride 272B)
__device__ __forceinline__ void epi_relu(float acc[4][4][4], const float* __restrict__ bias,
                                         char* smem, int lane, int wm, int wn) {
#pragma unroll
    for (int mt = 0; mt < 4; mt++)
#pragma unroll
        for (int nt = 0; nt < 4; nt++) {
            int n0 = wn * 32 + nt * 8 + (lane & 3) * 2;
            float2 bv = *(const float2*)(bias + n0);
            int r0 = wm * 64 + mt * 16 + (lane >> 2);
            float v0 = fmaxf(acc[mt][nt][0] + bv.x, 0.f);
            float v1 = fmaxf(acc[mt][nt][1] + bv.y, 0.f);
            float v2 = fmaxf(acc[mt][nt][2] + bv.x, 0.f);
            float v3 = fmaxf(acc[mt][nt][3] + bv.y, 0.f);
            *(uint32_t*)(smem + SM_H + r0 * 272 + n0 * 2) =
                hpack(__float2half_rn(v0), __float2half_rn(v1));
            *(uint32_t*)(smem + SM_H + (r0 + 8) * 272 + n0 * 2) =
                hpack(__float2half_rn(v2), __float2half_rn(v3));
        }
}

// layer3: bias only -> fp32 staging (stride 528B)
__device__ __forceinline__ void epi_f32(float acc[4][4][4], const float* __restrict__ bias,
                                        char* smem, int lane, int wm, int wn) {
#pragma unroll
    for (int mt = 0; mt < 4; mt++)
#pragma unroll
        for (int nt = 0; nt < 4; nt++) {
            int n0 = wn * 32 + nt * 8 + (lane & 3) * 2;
            float2 bv = *(const float2*)(bias + n0);
            int r0 = wm * 64 + mt * 16 + (lane >> 2);
            *(float2*)(smem + SM_STG + r0 * 528 + n0 * 4) =
                make_float2(acc[mt][nt][0] + bv.x, acc[mt][nt][1] + bv.y);
            *(float2*)(smem + SM_STG + (r0 + 8) * 528 + n0 * 4) =
                make_float2(acc[mt][nt][2] + bv.x, acc[mt][nt][3] + bv.y);
        }
}

// ---------------- P kernel: g_P[n] = [ nf.W1a | nf.W1b ], fp16 ----------------
__global__ void __launch_bounds__(256, 2) p_kernel(const float* __restrict__ nf) {
    extern __shared__ char smem[];
    const uint32_t sb = (uint32_t)__cvta_generic_to_shared(smem);
    const int tid = threadIdx.x, lane = tid & 31, wid = tid >> 5;
    const int wm = wid >> 2, wn = wid & 3;
    const size_t base = (size_t)blockIdx.x * 128;
    const int pass = blockIdx.y;            // 0: W1a (rows 0..128), 1: W1b (rows 128..256)
    const int grow = tid >> 1, q = tid & 1;

    float4 pre[4];
    auto ldg_chunk = [&](int g) {
        size_t ge = base + grow;
        bool zero = (ge >= NN);
        const float* src = nf + (zero ? 0 : ge * D) + g * 32 + q * 16;
#pragma unroll
        for (int i = 0; i < 4; i++)
            pre[i] = zero ? make_float4(0.f, 0.f, 0.f, 0.f) : *(const float4*)(src + i * 4);
    };
    auto sts_chunk = [&](int buf) {
        uint4 h0, h1;
        h0.x = hpack(__float2half_rn(pre[0].x), __float2half_rn(pre[0].y));
        h0.y = hpack(__float2half_rn(pre[0].z), __float2half_rn(pre[0].w));
        h0.z = hpack(__float2half_rn(pre[1].x), __float2half_rn(pre[1].y));
        h0.w = hpack(__float2half_rn(pre[1].z), __float2half_rn(pre[1].w));
        h1.x = hpack(__float2half_rn(pre[2].x), __float2half_rn(pre[2].y));
        h1.y = hpack(__float2half_rn(pre[2].z), __float2half_rn(pre[2].w));
        h1.z = hpack(__float2half_rn(pre[3].x), __float2half_rn(pre[3].y));
        h1.w = hpack(__float2half_rn(pre[3].z), __float2half_rn(pre[3].w));
        uint32_t off = XOFF(buf) + (uint32_t)grow * XSTR + (uint32_t)q * 32;
        *(uint4*)(smem + off)      = h0;
        *(uint4*)(smem + off + 16) = h1;
    };

    float acc[4][4][4];
#pragma unroll
    for (int mt = 0; mt < 4; mt++)
#pragma unroll
        for (int nt = 0; nt < 4; nt++)
#pragma unroll
            for (int i = 0; i < 4; i++) acc[mt][nt][i] = 0.f;

    const int WR0 = pass * 128;
    ldg_chunk(0); sts_chunk(0); ldg_chunk(1);
    stage_w(sb, WBUF(0), WR0, tid);
    stage_w(sb, WBUF(1), WR0 + 32, tid);
    cp_wait<1>();
    __syncthreads();

    for (int g = 0; g < 4; g++) {
        if (g + 1 < 4) sts_chunk((g + 1) & 1);
        if (g + 2 < 4) ldg_chunk(g + 2);
        if (g + 2 < 4) stage_w(sb, WBUF((g + 2) % 3), WR0 + (g + 2) * 32, tid);
        gemm_chunk(sb, XOFF(g & 1), XSTR, 0u, WBUF(g % 3), lane, wm, wn, acc);
        if (g + 2 < 4) cp_wait<1>(); else cp_wait<0>();
        __syncthreads();
    }

#pragma unroll
    for (int mt = 0; mt < 4; mt++)
#pragma unroll
        for (int nt = 0; nt < 4; nt++) {
            int n0 = wn * 32 + nt * 8 + (lane & 3) * 2;
            int r0 = wm * 64 + mt * 16 + (lane >> 2);
            if (base + r0 < NN)
                *(uint32_t*)&g_P[(base + r0) * 256 + pass * 128 + n0] =
                    hpack(__float2half_rn(acc[mt][nt][0]), __float2half_rn(acc[mt][nt][1]));
            if (base + r0 + 8 < NN)
                *(uint32_t*)&g_P[(base + r0 + 8) * 256 + pass * 128 + n0] =
                    hpack(__float2half_rn(acc[mt][nt][2]), __float2half_rn(acc[mt][nt][3]));
        }
}

// ---------------- main MLP kernels ----------------
template <bool EDGE>
__global__ void __launch_bounds__(256, 2) mlp_kernel(
    const float* __restrict__ nf, const float* __restrict__ ef,
    const int* __restrict__ snd, const int* __restrict__ rcv,
    const float* __restrict__ b1, const float* __restrict__ b2, const float* __restrict__ b3,
    const float* __restrict__ gamma, const float* __restrict__ beta,
    float* __restrict__ out) {
    extern __shared__ char smem[];
    const uint32_t sb = (uint32_t)__cvta_generic_to_shared(smem);
    const int tid = threadIdx.x, lane = tid & 31, wid = tid >> 5;
    const int wm = wid >> 2, wn = wid & 3;
    const size_t base = (size_t)blockIdx.x * 128;
    const size_t LIM = EDGE ? NE : NN;

    int* sidx = (int*)(smem + SM_IDXS);
    int* ridx = (int*)(smem + SM_IDXR);
    if (EDGE) {
        size_t ge = base + (tid & 127);
        int v = (ge < NE) ? ((tid < 128) ? snd[ge] : rcv[ge]) : 0;
        if (tid < 128) sidx[tid] = v; else ridx[tid - 128] = v;
    }
    __syncthreads();

    const int grow = tid >> 1, q = tid & 1;   // 2 threads/row, 16 floats (or 64 halves) each

    float acc[4][4][4];

    // ---- EDGE: coalesced P gather -> PSUM smem -> acc init ----
    if (EDGE) {
        {
            const uint4* pa = (const uint4*)(g_P + (size_t)sidx[grow] * 256) + q * 8;
            const uint4* pb = (const uint4*)(g_P + (size_t)ridx[grow] * 256 + 128) + q * 8;
            uint4* dst = (uint4*)(smem + SM_PSUM + (uint32_t)grow * 272 + (uint32_t)q * 128);
#pragma unroll
            for (int i = 0; i < 8; i++) {
                uint4 a = __ldg(pa + i), b = __ldg(pb + i);
                dst[i] = make_uint4(hadd2u(a.x, b.x), hadd2u(a.y, b.y),
                                    hadd2u(a.z, b.z), hadd2u(a.w, b.w));
            }
        }
        __syncthreads();
#pragma unroll
        for (int mt = 0; mt < 4; mt++) {
#pragma unroll
            for (int hh = 0; hh < 2; hh++) {
                int r = wm * 64 + mt * 16 + (lane >> 2) + hh * 8;
#pragma unroll
                for (int nt = 0; nt < 4; nt++) {
                    int n0 = wn * 32 + nt * 8 + (lane & 3) * 2;
                    __half2 s = *(const __half2*)(smem + SM_PSUM + (uint32_t)r * 272 + n0 * 2);
                    float2 f = __half22float2(s);
                    acc[mt][nt][hh * 2 + 0] = f.x;
                    acc[mt][nt][hh * 2 + 1] = f.y;
                }
            }
        }
        __syncthreads();   // PSUM dead; X/h region may now be written
    } else {
#pragma unroll
        for (int mt = 0; mt < 4; mt++)
#pragma unroll
            for (int nt = 0; nt < 4; nt++)
#pragma unroll
                for (int i = 0; i < 4; i++) acc[mt][nt][i] = 0.f;
    }

    float4 pre[4];                            // prefetched gather regs
    auto ldg_chunk = [&](int g) {
        const float* src;
        bool zero = false;
        size_t ge = base + grow;
        int col0 = (g & 3) * 32 + q * 16;
        if (EDGE) {                            // layer-1 input is ef only
            zero = (ge >= NE);
            src = ef + (zero ? 0 : ge * D) + col0;
        } else {
            int seg = g >> 2;
            zero = (ge >= NN);
            src = (seg == 0 ? nf : g_agg) + (zero ? 0 : ge * D) + col0;
        }
#pragma unroll
        for (int i = 0; i < 4; i++)
            pre[i] = zero ? make_float4(0.f, 0.f, 0.f, 0.f) : *(const float4*)(src + i * 4);
    };
    auto sts_chunk = [&](int buf) {
        uint4 h0, h1;
        h0.x = hpack(__float2half_rn(pre[0].x), __float2half_rn(pre[0].y));
        h0.y = hpack(__float2half_rn(pre[0].z), __float2half_rn(pre[0].w));
        h0.z = hpack(__float2half_rn(pre[1].x), __float2half_rn(pre[1].y));
        h0.w = hpack(__float2half_rn(pre[1].z), __float2half_rn(pre[1].w));
        h1.x = hpack(__float2half_rn(pre[2].x), __float2half_rn(pre[2].y));
        h1.y = hpack(__float2half_rn(pre[2].z), __float2half_rn(pre[2].w));
        h1.z = hpack(__float2half_rn(pre[3].x), __float2half_rn(pre[3].y));
        h1.w = hpack(__float2half_rn(pre[3].z), __float2half_rn(pre[3].w));
        uint32_t off = XOFF(buf) + (uint32_t)grow * XSTR + (uint32_t)q * 32;
        *(uint4*)(smem + off)      = h0;
        *(uint4*)(smem + off + 16) = h1;
    };

    const int L1 = EDGE ? 4 : 8;        // 32-k chunks in layer 1
    const int NCH = L1 + 8;             // + 4 (L2) + 4 (L3)
    const int WR0 = EDGE ? 256 : 640;   // first stacked weight row (edge: W1c)

    // ---- prologue: X chunks 0,1 and W chunks 0,1 in flight ----
    ldg_chunk(0);
    sts_chunk(0);
    ldg_chunk(1);
    stage_w(sb, WBUF(0), WR0, tid);
    stage_w(sb, WBUF(1), WR0 + 32, tid);
    cp_wait<1>();                        // W0 complete
    __syncthreads();

    // ---- fused chunk loop: ONE barrier per chunk ----
    for (int g = 0; g < NCH; g++) {
        if (g == L1 || g == L1 + 4) {    // layer boundary: write h, then barrier
            epi_relu(acc, (g == L1) ? b1 : b2, smem, lane, wm, wn);
#pragma unroll
            for (int mt = 0; mt < 4; mt++)
#pragma unroll
                for (int nt = 0; nt < 4; nt++)
#pragma unroll
                    for (int i = 0; i < 4; i++) acc[mt][nt][i] = 0.f;
            __syncthreads();
        }
        // prefetches — all independent of gemm(g)
        if (g + 1 < L1) sts_chunk((g + 1) & 1);          // regs hold chunk g+1
        if (g + 2 < L1) ldg_chunk(g + 2);
        if (g + 2 < NCH) stage_w(sb, WBUF((g + 2) % 3), WR0 + (g + 2) * 32, tid);

        if (g < L1) gemm_chunk(sb, XOFF(g & 1), XSTR, 0u, WBUF(g % 3), lane, wm, wn, acc);
        else gemm_chunk(sb, SM_H, 272u, (uint32_t)((g - L1) & 3) * 32u,
                        WBUF(g % 3), lane, wm, wn, acc);

        if (g + 2 < NCH) cp_wait<1>(); else cp_wait<0>();
        __syncthreads();                 // X(g+1), W(g+1) visible; gemm(g) done CTA-wide
    }

    epi_f32(acc, b3, smem, lane, wm, wn);   // staging aliases dead X+h+W
    __syncthreads();

    // LN + residual (+ scatter for edges): 16 threads/row, 8 rows per group
    const int ccg = tid & 15, ecg = tid >> 4;
    float4 g0 = *(const float4*)(gamma + ccg * 8), g1 = *(const float4*)(gamma + ccg * 8 + 4);
    float4 t0 = *(const float4*)(beta + ccg * 8),  t1 = *(const float4*)(beta + ccg * 8 + 4);
    float gv[8] = {g0.x, g0.y, g0.z, g0.w, g1.x, g1.y, g1.z, g1.w};
    float bv[8] = {t0.x, t0.y, t0.z, t0.w, t1.x, t1.y, t1.z, t1.w};
#pragma unroll
    for (int ei = 0; ei < 8; ei++) {
        int el = ecg * 8 + ei;
        size_t ge = base + el;
        float4 p0 = *(float4*)(smem + SM_STG + (uint32_t)el * 528 + ccg * 32);
        float4 p1 = *(float4*)(smem + SM_STG + (uint32_t)el * 528 + ccg * 32 + 16);
        float v[8] = {p0.x, p0.y, p0.z, p0.w, p1.x, p1.y, p1.z, p1.w};
        float s = 0.f, s2 = 0.f;
#pragma unroll
        for (int c = 0; c < 8; c++) { s += v[c]; s2 += v[c] * v[c]; }
#pragma unroll
        for (int m = 8; m >= 1; m >>= 1) {
            s  += __shfl_xor_sync(0xffffffffu, s, m);
            s2 += __shfl_xor_sync(0xffffffffu, s2, m);
        }
        if (ge >= LIM) continue;
        float mu = s * (1.f / D), var = s2 * (1.f / D) - mu * mu;
        float rstd = rsqrtf(fmaxf(var, 0.f) + 1e-5f);
        float nrm[8];
#pragma unroll
        for (int c = 0; c < 8; c++) nrm[c] = (v[c] - mu) * rstd * gv[c] + bv[c];
        if (EDGE) {
            float* ap = g_agg + (size_t)ridx[el] * D + ccg * 8;
            asm volatile("red.global.add.v4.f32 [%0], {%1,%2,%3,%4};" ::
                         "l"(ap), "f"(nrm[0]), "f"(nrm[1]), "f"(nrm[2]), "f"(nrm[3]) : "memory");
            asm volatile("red.global.add.v4.f32 [%0], {%1,%2,%3,%4};" ::
                         "l"(ap + 4), "f"(nrm[4]), "f"(nrm[5]), "f"(nrm[6]), "f"(nrm[7]) : "memory");
        }
        const float* res = (EDGE ? ef : nf) + ge * D + ccg * 8;
        float4 e0 = *(const float4*)res, e1 = *(const float4*)(res + 4);
        float* op = out + ge * D + ccg * 8;
        *(float4*)op       = make_float4(nrm[0] + e0.x, nrm[1] + e0.y, nrm[2] + e0.z, nrm[3] + e0.w);
        *(float4*)(op + 4) = make_float4(nrm[4] + e1.x, nrm[5] + e1.y, nrm[6] + e1.z, nrm[7] + e1.w);
    }
}

extern "C" void kernel_launch(void* const* d_in, const int* in_sizes, int n_in,
                              void* d_out, int out_size) {
    const float* nf  = (const float*)d_in[0];
    const float* ef  = (const float*)d_in[1];
    const int*   snd = (const int*)d_in[2];
    const int*   rcv = (const int*)d_in[3];
    const float* ew1 = (const float*)d_in[4];
    const float* eb1 = (const float*)d_in[5];
    const float* ew2 = (const float*)d_in[6];
    const float* eb2 = (const float*)d_in[7];
    const float* ew3 = (const float*)d_in[8];
    const float* eb3 = (const float*)d_in[9];
    const float* eg  = (const float*)d_in[10];
    const float* ebt = (const float*)d_in[11];
    const float* nw1 = (const float*)d_in[12];
    const float* nb1 = (const float*)d_in[13];
    const float* nw2 = (const float*)d_in[14];
    const float* nb2 = (const float*)d_in[15];
    const float* nw3 = (const float*)d_in[16];
    const float* nb3 = (const float*)d_in[17];
    const float* ng  = (const float*)d_in[18];
    const float* nbt = (const float*)d_in[19];

    float* out_n = (float*)d_out;
    float* out_e = out_n + (size_t)NN * D;

    cudaFuncSetAttribute(mlp_kernel<true>,  cudaFuncAttributeMaxDynamicSharedMemorySize, SMEM_TOTAL);
    cudaFuncSetAttribute(mlp_kernel<false>, cudaFuncAttributeMaxDynamicSharedMemorySize, SMEM_TOTAL);
    cudaFuncSetAttribute(p_kernel, cudaFuncAttributeMaxDynamicSharedMemorySize, SMEM_TOTAL);

    prep_weights<<<612, 256>>>(ew1, ew2, ew3, nw1, nw2, nw3);
    zero_agg_kernel<<<NN * D / 4 / 256, 256>>>();
    p_kernel<<<dim3((NN + 127) / 128, 2), 256, SMEM_TOTAL>>>(nf);
    mlp_kernel<true><<<(NE + 127) / 128, 256, SMEM_TOTAL>>>(nf, ef, snd, rcv,
                                                            eb1, eb2, eb3, eg, ebt, out_e);
    mlp_kernel<false><<<(NN + 127) / 128, 256, SMEM_TOTAL>>>(nf, ef, snd, rcv,
                                                             nb1, nb2, nb3, ng, nbt, out_n);
}

// round 16
// speedup vs baseline: 1.2653x; 1.0353x over previous
#include <cuda_runtime.h>
#include <cuda_fp16.h>
#include <cstdint>

#define NN 100000
#define NE 600000
#define D  128
#define WPAD 136            // weight row width (272B rows)

// smem (bytes): X0 0 | X1 5120 | h 10240(17408) | W0/W1/W2 27648+i*8704 | idx 53760.
// PSUM (64 x 272B = 17408) aliases X0/X1/h-head (consumed before prologue).
// LN staging (64*528=33792) aliases X+h+W0-head (dead after layer-3 gemm).
#define XSTR   80u
#define XOFF(b) ((uint32_t)(b) * 5120u)
#define SM_H    10240u
#define WBUF(i) (27648u + (uint32_t)(i) * 8704u)
#define SM_STG  0u
#define SM_PSUM 0u
#define SM_IDXS 53760u
#define SM_IDXR 54016u
#define SMEM_TOTAL 54272

__device__ float g_agg[(size_t)NN * D];
// stacked fp16 weights (rows x 272B): [0,384) ew1 (W1a|W1b|W1c) | [384,512) ew2 |
// [512,640) ew3 | [640,896) nw1[0:256] | [896,1024) nw2 | [1024,1152) nw3
__device__ __half g_w[1152 * WPAD];
// precomputed node projections, fp16: row n = [ P_a(n)=nf.W1a (128) | P_b(n)=nf.W1b (128) ]
__device__ __half g_P[(size_t)NN * 256];

__global__ void zero_agg_kernel() {
    size_t i = (size_t)blockIdx.x * blockDim.x + threadIdx.x;
    ((float4*)g_agg)[i] = make_float4(0.f, 0.f, 0.f, 0.f);
}

__global__ void prep_weights(const float* __restrict__ ew1, const float* __restrict__ ew2,
                             const float* __restrict__ ew3, const float* __restrict__ nw1,
                             const float* __restrict__ nw2, const float* __restrict__ nw3) {
    int idx = blockIdx.x * 256 + threadIdx.x;
    if (idx >= 1152 * WPAD) return;
    int r = idx / WPAD, c = idx % WPAD;
    float v = 0.f;
    if (c < 128) {
        if (r < 384)       v = ew1[r * 128 + c];
        else if (r < 512)  v = ew2[(r - 384) * 128 + c];
        else if (r < 640)  v = ew3[(r - 512) * 128 + c];
        else if (r < 896)  v = nw1[(r - 640) * 128 + c];
        else if (r < 1024) v = nw2[(r - 896) * 128 + c];
        else               v = nw3[(r - 1024) * 128 + c];
    }
    g_w[idx] = __float2half_rn(v);
}

// ---------------- helpers ----------------
__device__ __forceinline__ void mma16816(float* c, const uint32_t* a, const uint32_t* b) {
    asm volatile(
        "mma.sync.aligned.m16n8k16.row.col.f32.f16.f16.f32 "
        "{%0,%1,%2,%3}, {%4,%5,%6,%7}, {%8,%9}, {%0,%1,%2,%3};"
        : "+f"(c[0]), "+f"(c[1]), "+f"(c[2]), "+f"(c[3])
        : "r"(a[0]), "r"(a[1]), "r"(a[2]), "r"(a[3]), "r"(b[0]), "r"(b[1]));
}
__device__ __forceinline__ void ldm_a(uint32_t* r, uint32_t addr) {
    asm volatile("ldmatrix.sync.aligned.m8n8.x4.shared.b16 {%0,%1,%2,%3}, [%4];"
                 : "=r"(r[0]), "=r"(r[1]), "=r"(r[2]), "=r"(r[3]) : "r"(addr));
}
__device__ __forceinline__ void ldm_bt4(uint32_t* r, uint32_t addr) {
    asm volatile("ldmatrix.sync.aligned.m8n8.x4.trans.shared.b16 {%0,%1,%2,%3}, [%4];"
                 : "=r"(r[0]), "=r"(r[1]), "=r"(r[2]), "=r"(r[3]) : "r"(addr));
}
__device__ __forceinline__ void cp16(uint32_t s, const void* g) {
    asm volatile("cp.async.cg.shared.global [%0], [%1], 16;" :: "r"(s), "l"(g));
}
#define CP_COMMIT() asm volatile("cp.async.commit_group;")
template <int N>
__device__ __forceinline__ void cp_wait() { asm volatile("cp.async.wait_group %0;" :: "n"(N)); }

__device__ __forceinline__ uint32_t hpack(__half a, __half b) {
    __half2 t = __halves2half2(a, b);
    return *reinterpret_cast<uint32_t*>(&t);
}
__device__ __forceinline__ uint32_t hadd2u(uint32_t a, uint32_t b) {
    __half2 r = __hadd2(*reinterpret_cast<__half2*>(&a), *reinterpret_cast<__half2*>(&b));
    return *reinterpret_cast<uint32_t*>(&r);
}

// stage one 32-row fp16 weight chunk (8704B) via cp.async
__device__ __forceinline__ void stage_w(uint32_t sb, uint32_t woff, int wrow, int tid) {
    const char* sw = (const char*)(g_w + (size_t)wrow * WPAD);
#pragma unroll
    for (int i = 0; i < 3; i++) {
        int j = tid + i * 256;
        if (j < 544) cp16(sb + woff + (uint32_t)j * 16, sw + j * 16);
    }
    CP_COMMIT();
}

// one 32-k chunk: acc[2][4][4] += A[64 x 32] * W[32 x 128]  (warp tile 32x32)
__device__ __forceinline__ void gemm_chunk(uint32_t sb, uint32_t a_off, uint32_t astr,
                                           uint32_t kbase, uint32_t w_off,
                                           int lane, int wm, int wn, float acc[2][4][4]) {
    uint32_t bw[4][4];
    uint32_t brow = (uint32_t)lane * 272u;
#pragma unroll
    for (int nt = 0; nt < 4; nt++) {
        uint32_t nb = (uint32_t)(wn * 32 + nt * 8) * 2;
        ldm_bt4(bw[nt], sb + w_off + brow + nb);
    }
#pragma unroll
    for (int ks = 0; ks < 2; ks++) {
        uint32_t ah[2][4];
        uint32_t colb = (kbase + (uint32_t)ks * 16 + (uint32_t)((lane >> 4) << 3)) * 2;
#pragma unroll
        for (int mt = 0; mt < 2; mt++) {
            uint32_t row = (uint32_t)(wm * 32 + mt * 16 + (lane & 15));
            ldm_a(ah[mt], sb + a_off + row * astr + colb);
        }
#pragma unroll
        for (int mt = 0; mt < 2; mt++)
#pragma unroll
            for (int nt = 0; nt < 4; nt++)
                mma16816(acc[mt][nt], ah[mt], &bw[nt][ks * 2]);
    }
}

// bias + relu -> fp16 h image (stride 272B)
__device__ __forceinline__ void epi_relu(float acc[2][4][4], const float* __restrict__ bias,
                                         char* smem, int lane, int wm, int wn) {
#pragma unroll
    for (int mt = 0; mt < 2; mt++)
#pragma unroll
        for (int nt = 0; nt < 4; nt++) {
            int n0 = wn * 32 + nt * 8 + (lane & 3) * 2;
            float2 bv = *(const float2*)(bias + n0);
            int r0 = wm * 32 + mt * 16 + (lane >> 2);
            float v0 = fmaxf(acc[mt][nt][0] + bv.x, 0.f);
            float v1 = fmaxf(acc[mt][nt][1] + bv.y, 0.f);
            float v2 = fmaxf(acc[mt][nt][2] + bv.x, 0.f);
            float v3 = fmaxf(acc[mt][nt][3] + bv.y, 0.f);
            *(uint32_t*)(smem + SM_H + r0 * 272 + n0 * 2) =
                hpack(__float2half_rn(v0), __float2half_rn(v1));
            *(uint32_t*)(smem + SM_H + (r0 + 8) * 272 + n0 * 2) =
                hpack(__float2half_rn(v2), __float2half_rn(v3));
        }
}

// layer3: bias only -> fp32 staging (stride 528B)
__device__ __forceinline__ void epi_f32(float acc[2][4][4], const float* __restrict__ bias,
                                        char* smem, int lane, int wm, int wn) {
#pragma unroll
    for (int mt = 0; mt < 2; mt++)
#pragma unroll
        for (int nt = 0; nt < 4; nt++) {
            int n0 = wn * 32 + nt * 8 + (lane & 3) * 2;
            float2 bv = *(const float2*)(bias + n0);
            int r0 = wm * 32 + mt * 16 + (lane >> 2);
            *(float2*)(smem + SM_STG + r0 * 528 + n0 * 4) =
                make_float2(acc[mt][nt][0] + bv.x, acc[mt][nt][1] + bv.y);
            *(float2*)(smem + SM_STG + (r0 + 8) * 528 + n0 * 4) =
                make_float2(acc[mt][nt][2] + bv.x, acc[mt][nt][3] + bv.y);
        }
}

// ---------------- P kernel: g_P[n] = [ nf.W1a | nf.W1b ], fp16, M=64 ----------------
__global__ void __launch_bounds__(256, 3) p_kernel(const float* __restrict__ nf) {
    extern __shared__ char smem[];
    const uint32_t sb = (uint32_t)__cvta_generic_to_shared(smem);
    const int tid = threadIdx.x, lane = tid & 31, wid = tid >> 5;
    const int wm = wid >> 2, wn = wid & 3;
    const size_t base = (size_t)blockIdx.x * 64;
    const int pass = blockIdx.y;            // 0: W1a, 1: W1b
    const int grow = tid >> 2, q = tid & 3;

    float4 pre0, pre1;
    auto ldg_chunk = [&](int g) {
        size_t ge = base + grow;
        bool zero = (ge >= NN);
        const float* src = nf + (zero ? 0 : ge * D) + g * 32;
        pre0 = zero ? make_float4(0.f, 0.f, 0.f, 0.f) : *(const float4*)(src + q * 8);
        pre1 = zero ? make_float4(0.f, 0.f, 0.f, 0.f) : *(const float4*)(src + q * 8 + 4);
    };
    auto sts_chunk = [&](int buf) {
        uint4 h;
        h.x = hpack(__float2half_rn(pre0.x), __float2half_rn(pre0.y));
        h.y = hpack(__float2half_rn(pre0.z), __float2half_rn(pre0.w));
        h.z = hpack(__float2half_rn(pre1.x), __float2half_rn(pre1.y));
        h.w = hpack(__float2half_rn(pre1.z), __float2half_rn(pre1.w));
        *(uint4*)(smem + XOFF(buf) + (uint32_t)grow * XSTR + (uint32_t)q * 16) = h;
    };

    float acc[2][4][4];
#pragma unroll
    for (int mt = 0; mt < 2; mt++)
#pragma unroll
        for (int nt = 0; nt < 4; nt++)
#pragma unroll
            for (int i = 0; i < 4; i++) acc[mt][nt][i] = 0.f;

    const int WR0 = pass * 128;
    ldg_chunk(0); sts_chunk(0); ldg_chunk(1);
    stage_w(sb, WBUF(0), WR0, tid);
    stage_w(sb, WBUF(1), WR0 + 32, tid);
    cp_wait<1>();
    __syncthreads();

    for (int g = 0; g < 4; g++) {
        if (g + 1 < 4) sts_chunk((g + 1) & 1);
        if (g + 2 < 4) ldg_chunk(g + 2);
        if (g + 2 < 4) stage_w(sb, WBUF((g + 2) % 3), WR0 + (g + 2) * 32, tid);
        gemm_chunk(sb, XOFF(g & 1), XSTR, 0u, WBUF(g % 3), lane, wm, wn, acc);
        if (g + 2 < 4) cp_wait<1>(); else cp_wait<0>();
        __syncthreads();
    }

#pragma unroll
    for (int mt = 0; mt < 2; mt++)
#pragma unroll
        for (int nt = 0; nt < 4; nt++) {
            int n0 = wn * 32 + nt * 8 + (lane & 3) * 2;
            int r0 = wm * 32 + mt * 16 + (lane >> 2);
            if (base + r0 < NN)
                *(uint32_t*)&g_P[(base + r0) * 256 + pass * 128 + n0] =
                    hpack(__float2half_rn(acc[mt][nt][0]), __float2half_rn(acc[mt][nt][1]));
            if (base + r0 + 8 < NN)
                *(uint32_t*)&g_P[(base + r0 + 8) * 256 + pass * 128 + n0] =
                    hpack(__float2half_rn(acc[mt][nt][2]), __float2half_rn(acc[mt][nt][3]));
        }
}

// ---------------- main MLP kernels (M=64, occ 3) ----------------
template <bool EDGE>
__global__ void __launch_bounds__(256, 3) mlp_kernel(
    const float* __restrict__ nf, const float* __restrict__ ef,
    const int* __restrict__ snd, const int* __restrict__ rcv,
    const float* __restrict__ b1, const float* __restrict__ b2, const float* __restrict__ b3,
    const float* __restrict__ gamma, const float* __restrict__ beta,
    float* __restrict__ out) {
    extern __shared__ char smem[];
    const uint32_t sb = (uint32_t)__cvta_generic_to_shared(smem);
    const int tid = threadIdx.x, lane = tid & 31, wid = tid >> 5;
    const int wm = wid >> 2, wn = wid & 3;
    const size_t base = (size_t)blockIdx.x * 64;
    const size_t LIM = EDGE ? NE : NN;

    int* sidx = (int*)(smem + SM_IDXS);
    int* ridx = (int*)(smem + SM_IDXR);
    if (EDGE && tid < 128) {
        size_t ge = base + (tid & 63);
        int v = (ge < NE) ? ((tid < 64) ? snd[ge] : rcv[ge]) : 0;
        if (tid < 64) sidx[tid] = v; else ridx[tid - 64] = v;
    }
    __syncthreads();

    const int grow = tid >> 2, q = tid & 3;   // 4 threads/row

    float acc[2][4][4];

    // ---- EDGE: coalesced P gather -> PSUM smem -> acc init ----
    if (EDGE) {
        {
            const uint4* pa = (const uint4*)(g_P + (size_t)sidx[grow] * 256) + q * 4;
            const uint4* pb = (const uint4*)(g_P + (size_t)ridx[grow] * 256 + 128) + q * 4;
            uint4* dst = (uint4*)(smem + SM_PSUM + (uint32_t)grow * 272 + (uint32_t)q * 64);
#pragma unroll
            for (int i = 0; i < 4; i++) {
                uint4 a = __ldg(pa + i), b = __ldg(pb + i);
                dst[i] = make_uint4(hadd2u(a.x, b.x), hadd2u(a.y, b.y),
                                    hadd2u(a.z, b.z), hadd2u(a.w, b.w));
            }
        }
        __syncthreads();
#pragma unroll
        for (int mt = 0; mt < 2; mt++) {
#pragma unroll
            for (int hh = 0; hh < 2; hh++) {
                int r = wm * 32 + mt * 16 + (lane >> 2) + hh * 8;
#pragma unroll
                for (int nt = 0; nt < 4; nt++) {
                    int n0 = wn * 32 + nt * 8 + (lane & 3) * 2;
                    __half2 s = *(const __half2*)(smem + SM_PSUM + (uint32_t)r * 272 + n0 * 2);
                    float2 f = __half22float2(s);
                    acc[mt][nt][hh * 2 + 0] = f.x;
                    acc[mt][nt][hh * 2 + 1] = f.y;
                }
            }
        }
        __syncthreads();   // PSUM dead; X/h region may now be written
    } else {
#pragma unroll
        for (int mt = 0; mt < 2; mt++)
#pragma unroll
            for (int nt = 0; nt < 4; nt++)
#pragma unroll
                for (int i = 0; i < 4; i++) acc[mt][nt][i] = 0.f;
    }

    float4 pre0, pre1;                        // prefetched gather regs
    auto ldg_chunk = [&](int g) {
        const float* src;
        bool zero = false;
        size_t ge = base + grow;
        if (EDGE) {                            // layer-1 input is ef only (4 chunks)
            zero = (ge >= NE);
            src = ef + (zero ? 0 : ge * D) + g * 32;
        } else {
            int seg = g >> 2;
            zero = (ge >= NN);
            src = (seg == 0 ? nf : g_agg) + (zero ? 0 : ge * D) + (g & 3) * 32;
        }
        pre0 = zero ? make_float4(0.f, 0.f, 0.f, 0.f) : *(const float4*)(src + q * 8);
        pre1 = zero ? make_float4(0.f, 0.f, 0.f, 0.f) : *(const float4*)(src + q * 8 + 4);
    };
    auto sts_chunk = [&](int buf) {
        uint4 h;
        h.x = hpack(__float2half_rn(pre0.x), __float2half_rn(pre0.y));
        h.y = hpack(__float2half_rn(pre0.z), __float2half_rn(pre0.w));
        h.z = hpack(__float2half_rn(pre1.x), __float2half_rn(pre1.y));
        h.w = hpack(__float2half_rn(pre1.z), __float2half_rn(pre1.w));
        *(uint4*)(smem + XOFF(buf) + (uint32_t)grow * XSTR + (uint32_t)q * 16) = h;
    };

    const int L1 = EDGE ? 4 : 8;        // 32-k chunks in layer 1
    const int NCH = L1 + 8;             // + 4 (L2) + 4 (L3)
    const int WR0 = EDGE ? 256 : 640;   // first stacked weight row (edge: W1c)

    // ---- prologue: X chunks 0,1 and W chunks 0,1 in flight ----
    ldg_chunk(0);
    sts_chunk(0);
    ldg_chunk(1);
    stage_w(sb, WBUF(0), WR0, tid);
    stage_w(sb, WBUF(1), WR0 + 32, tid);
    cp_wait<1>();                        // W0 complete
    __syncthreads();

    // ---- fused chunk loop: ONE barrier per chunk ----
    for (int g = 0; g < NCH; g++) {
        if (g == L1 || g == L1 + 4) {    // layer boundary: write h, then barrier
            epi_relu(acc, (g == L1) ? b1 : b2, smem, lane, wm, wn);
#pragma unroll
            for (int mt = 0; mt < 2; mt++)
#pragma unroll
                for (int nt = 0; nt < 4; nt++)
#pragma unroll
                    for (int i = 0; i < 4; i++) acc[mt][nt][i] = 0.f;
            __syncthreads();
        }
        // prefetches — all independent of gemm(g)
        if (g + 1 < L1) sts_chunk((g + 1) & 1);          // regs hold chunk g+1
        if (g + 2 < L1) ldg_chunk(g + 2);
        if (g + 2 < NCH) stage_w(sb, WBUF((g + 2) % 3), WR0 + (g + 2) * 32, tid);

        if (g < L1) gemm_chunk(sb, XOFF(g & 1), XSTR, 0u, WBUF(g % 3), lane, wm, wn, acc);
        else gemm_chunk(sb, SM_H, 272u, (uint32_t)((g - L1) & 3) * 32u,
                        WBUF(g % 3), lane, wm, wn, acc);

        if (g + 2 < NCH) cp_wait<1>(); else cp_wait<0>();
        __syncthreads();                 // X(g+1), W(g+1) visible; gemm(g) done CTA-wide
    }

    epi_f32(acc, b3, smem, lane, wm, wn);   // staging aliases dead X+h+W0-head
    __syncthreads();

    // LN + residual (+ scatter for edges): 16 threads/row, 4 rows per group
    const int ccg = tid & 15, ecg = tid >> 4;
    float4 g0 = *(const float4*)(gamma + ccg * 8), g1 = *(const float4*)(gamma + ccg * 8 + 4);
    float4 t0 = *(const float4*)(beta + ccg * 8),  t1 = *(const float4*)(beta + ccg * 8 + 4);
    float gv[8] = {g0.x, g0.y, g0.z, g0.w, g1.x, g1.y, g1.z, g1.w};
    float bv[8] = {t0.x, t0.y, t0.z, t0.w, t1.x, t1.y, t1.z, t1.w};
#pragma unroll
    for (int ei = 0; ei < 4; ei++) {
        int el = ecg * 4 + ei;
        size_t ge = base + el;
        float4 p0 = *(float4*)(smem + SM_STG + (uint32_t)el * 528 + ccg * 32);
        float4 p1 = *(float4*)(smem + SM_STG + (uint32_t)el * 528 + ccg * 32 + 16);
        float v[8] = {p0.x, p0.y, p0.z, p0.w, p1.x, p1.y, p1.z, p1.w};
        float s = 0.f, s2 = 0.f;
#pragma unroll
        for (int c = 0; c < 8; c++) { s += v[c]; s2 += v[c] * v[c]; }
#pragma unroll
        for (int m = 8; m >= 1; m >>= 1) {
            s  += __shfl_xor_sync(0xffffffffu, s, m);
            s2 += __shfl_xor_sync(0xffffffffu, s2, m);
        }
        if (ge >= LIM) continue;
        float mu = s * (1.f / D), var = s2 * (1.f / D) - mu * mu;
        float rstd = rsqrtf(fmaxf(var, 0.f) + 1e-5f);
        float nrm[8];
#pragma unroll
        for (int c = 0; c < 8; c++) nrm[c] = (v[c] - mu) * rstd * gv[c] + bv[c];
        if (EDGE) {
            float* ap = g_agg + (size_t)ridx[el] * D + ccg * 8;
            asm volatile("red.global.add.v4.f32 [%0], {%1,%2,%3,%4};" ::
                         "l"(ap), "f"(nrm[0]), "f"(nrm[1]), "f"(nrm[2]), "f"(nrm[3]) : "memory");
            asm volatile("red.global.add.v4.f32 [%0], {%1,%2,%3,%4};" ::
                         "l"(ap + 4), "f"(nrm[4]), "f"(nrm[5]), "f"(nrm[6]), "f"(nrm[7]) : "memory");
        }
        const float* res = (EDGE ? ef : nf) + ge * D + ccg * 8;
        float4 e0 = *(const float4*)res, e1 = *(const float4*)(res + 4);
        float* op = out + ge * D + ccg * 8;
        *(float4*)op       = make_float4(nrm[0] + e0.x, nrm[1] + e0.y, nrm[2] + e0.z, nrm[3] + e0.w);
        *(float4*)(op + 4) = make_float4(nrm[4] + e1.x, nrm[5] + e1.y, nrm[6] + e1.z, nrm[7] + e1.w);
    }
}

extern "C" void kernel_launch(void* const* d_in, const int* in_sizes, int n_in,
                              void* d_out, int out_size) {
    const float* nf  = (const float*)d_in[0];
    const float* ef  = (const float*)d_in[1];
    const int*   snd = (const int*)d_in[2];
    const int*   rcv = (const int*)d_in[3];
    const float* ew1 = (const float*)d_in[4];
    const float* eb1 = (const float*)d_in[5];
    const float* ew2 = (const float*)d_in[6];
    const float* eb2 = (const float*)d_in[7];
    const float* ew3 = (const float*)d_in[8];
    const float* eb3 = (const float*)d_in[9];
    const float* eg  = (const float*)d_in[10];
    const float* ebt = (const float*)d_in[11];
    const float* nw1 = (const float*)d_in[12];
    const float* nb1 = (const float*)d_in[13];
    const float* nw2 = (const float*)d_in[14];
    const float* nb2 = (const float*)d_in[15];
    const float* nw3 = (const float*)d_in[16];
    const float* nb3 = (const float*)d_in[17];
    const float* ng  = (const float*)d_in[18];
    const float* nbt = (const float*)d_in[19];

    float* out_n = (float*)d_out;
    float* out_e = out_n + (size_t)NN * D;

    cudaFuncSetAttribute(mlp_kernel<true>,  cudaFuncAttributeMaxDynamicSharedMemorySize, SMEM_TOTAL);
    cudaFuncSetAttribute(mlp_kernel<false>, cudaFuncAttributeMaxDynamicSharedMemorySize, SMEM_TOTAL);
    cudaFuncSetAttribute(p_kernel, cudaFuncAttributeMaxDynamicSharedMemorySize, SMEM_TOTAL);

    prep_weights<<<612, 256>>>(ew1, ew2, ew3, nw1, nw2, nw3);
    zero_agg_kernel<<<NN * D / 4 / 256, 256>>>();
    p_kernel<<<dim3((NN + 63) / 64, 2), 256, SMEM_TOTAL>>>(nf);
    mlp_kernel<true><<<(NE + 63) / 64, 256, SMEM_TOTAL>>>(nf, ef, snd, rcv,
                                                          eb1, eb2, eb3, eg, ebt, out_e);
    mlp_kernel<false><<<(NN + 63) / 64, 256, SMEM_TOTAL>>>(nf, ef, snd, rcv,
                                                           nb1, nb2, nb3, ng, nbt, out_n);
}